// round 10
// baseline (speedup 1.0000x reference)
#include <cuda_runtime.h>
#include <cstdint>

// ---------------------------------------------------------------------------
// Sparse CNN backbone, fp32, SoA [C][n] features, 3-way K-split convs:
// taps split across 3 CTA sets writing partials za/zb/zc; elementwise
// passes consume (za+zb+zc). ~4.7 CTAs/SM during convs.
// ---------------------------------------------------------------------------

#define MAXN2 80000
#define MAXN4 13824
#define NB 64   // stats blocks per channel

__device__ float g_xc[MAXN2 * 32];
__device__ float g_za[MAXN2 * 32];
__device__ float g_zb[MAXN2 * 32];
__device__ float g_zc[MAXN2 * 32];
__device__ float g_xt[MAXN2 * 32];
__device__ float g_y[MAXN4 * 64];
__device__ float g_part[64 * NB * 2];
__device__ float g_par[128];

typedef unsigned long long ull;

__device__ __forceinline__ ull pack2(float x) {
    ull r;
    asm("mov.b64 %0, {%1, %1};" : "=l"(r) : "f"(x));
    return r;
}
__device__ __forceinline__ void fma2(ull& d, ull a, ull b) {
    asm("fma.rn.f32x2 %0, %1, %2, %0;" : "+l"(d) : "l"(a), "l"(b));
}

// ---------------------------------------------------------------------------
// 3-way K-split SoA conv. fT [CIN][n_in] -> za|zb|zc [COUT][n_out] partials.
// blockIdx.z in {0,1,2} selects tap range [..KA),[KA,KB),[KB,K).
// blockIdx.y slices COUT by SLICE. Thread = 1 row x SLICE; 256 rows/CTA.
// ---------------------------------------------------------------------------
template <int CIN, int SLICE>
__global__ __launch_bounds__(256, 3) void conv_k(
    const float* __restrict__ fT, const float* __restrict__ W,
    const int* __restrict__ in_map, int n_in, int n_out, int COUT,
    int K, int KA, int KB, float* __restrict__ oTa, float* __restrict__ oTb,
    float* __restrict__ oTc) {
    extern __shared__ float sW[];
    const int tid = threadIdx.x;
    const int yoff = blockIdx.y * SLICE;
    const int z = blockIdx.z;
    const int k0 = (z == 0) ? 0 : (z == 1 ? KA : KB);
    const int k1 = (z == 0) ? KA : (z == 1 ? KB : K);
    const int taps = k1 - k0;
    constexpr int WV = SLICE / 4;

    for (int i = tid; i < taps * CIN * WV; i += 256) {
        int r = i / WV, c4 = (i % WV) * 4;
        reinterpret_cast<float4*>(sW)[i] = *reinterpret_cast<const float4*>(
            W + ((size_t)k0 * CIN + r) * COUT + yoff + c4);
    }
    __syncthreads();

    const int row = blockIdx.x * 256 + tid;
    const bool rowok = row < n_out;
    float* __restrict__ oT = (z == 0) ? oTa : (z == 1 ? oTb : oTc);

    ull acc[SLICE / 2];
#pragma unroll
    for (int i = 0; i < SLICE / 2; i++) acc[i] = 0ull;

    int idxn = rowok ? __ldg(&in_map[(size_t)k0 * n_out + row]) : n_in;
    for (int k = k0; k < k1; k++) {
        const int idx = idxn;
        if (k + 1 < k1)
            idxn = rowok ? __ldg(&in_map[(size_t)(k + 1) * n_out + row]) : n_in;
        if (idx >= n_in) continue;

        const float* wk = sW + (size_t)(k - k0) * CIN * SLICE;
#pragma unroll
        for (int cc = 0; cc < CIN / 8; cc++) {
            float x[8];
#pragma unroll
            for (int j = 0; j < 8; j++)
                x[j] = __ldg(fT + (size_t)(cc * 8 + j) * n_in + idx);
#pragma unroll
            for (int j = 0; j < 8; j++) {
                ull a2 = pack2(x[j]);
                const ulonglong2* wr = reinterpret_cast<const ulonglong2*>(
                    wk + (cc * 8 + j) * SLICE);
#pragma unroll
                for (int p = 0; p < SLICE / 4; p++) {
                    ulonglong2 w = wr[p];
                    fma2(acc[2 * p], a2, w.x);
                    fma2(acc[2 * p + 1], a2, w.y);
                }
            }
        }
    }

    if (rowok) {
#pragma unroll
        for (int p = 0; p < SLICE / 2; p++) {
            float2 v = *reinterpret_cast<float2*>(&acc[p]);
            oT[(size_t)(yoff + 2 * p) * n_out + row] = v.x;
            oT[(size_t)(yoff + 2 * p + 1) * n_out + row] = v.y;
        }
    }
}

// ---------------------------------------------------------------------------
// First conv, 3-way K-split: CIN=4, COUT=32, K=125.
// ---------------------------------------------------------------------------
__global__ __launch_bounds__(256, 3) void conv1_k(
    const float* __restrict__ geo, const float* __restrict__ col,
    const float* __restrict__ W, const int* __restrict__ in_map, int n_in,
    int n_out, int KA, int KB, float* __restrict__ oTa,
    float* __restrict__ oTb, float* __restrict__ oTc) {
    extern __shared__ float sm[];
    const int tid = threadIdx.x;
    const int z = blockIdx.z;
    const int k0 = (z == 0) ? 0 : (z == 1 ? KA : KB);
    const int k1 = (z == 0) ? KA : (z == 1 ? KB : 125);
    const int taps = k1 - k0;

    for (int i = tid; i < taps * 32; i += 256)
        reinterpret_cast<float4*>(sm)[i] =
            reinterpret_cast<const float4*>(W + (size_t)k0 * 128)[i];
    __syncthreads();

    const int row = blockIdx.x * 256 + tid;
    if (row >= n_out) return;
    float* __restrict__ oT = (z == 0) ? oTa : (z == 1 ? oTb : oTc);

    ull acc[16];
#pragma unroll
    for (int i = 0; i < 16; i++) acc[i] = 0ull;

    int idxn = __ldg(&in_map[(size_t)k0 * n_out + row]);
    for (int k = k0; k < k1; k++) {
        int idx = idxn;
        if (k + 1 < k1) idxn = __ldg(&in_map[(size_t)(k + 1) * n_out + row]);
        if (idx >= n_in) continue;

        float fr[4];
        fr[0] = __ldg(&geo[idx]);
        fr[1] = __ldg(&col[(size_t)idx * 3]);
        fr[2] = __ldg(&col[(size_t)idx * 3 + 1]);
        fr[3] = __ldg(&col[(size_t)idx * 3 + 2]);
        const float* wk = sm + (k - k0) * 128;
#pragma unroll
        for (int c = 0; c < 4; c++) {
            ull a2 = pack2(fr[c]);
            const ulonglong2* wrow = reinterpret_cast<const ulonglong2*>(wk + c * 32);
#pragma unroll
            for (int p = 0; p < 8; p++) {
                ulonglong2 w = wrow[p];
                fma2(acc[2 * p], a2, w.x);
                fma2(acc[2 * p + 1], a2, w.y);
            }
        }
    }
#pragma unroll
    for (int p = 0; p < 16; p++) {
        float2 v = *reinterpret_cast<float2*>(&acc[p]);
        oT[(size_t)(2 * p) * n_out + row] = v.x;
        oT[(size_t)(2 * p + 1) * n_out + row] = v.y;
    }
}

// ---------------------------------------------------------------------------
// Per-(channel, block) stats of (a+b+c): part[(ch*NB + bx)*2 +{0,1}].
// ---------------------------------------------------------------------------
__global__ __launch_bounds__(256) void stats3(
    const float* __restrict__ a, const float* __restrict__ b,
    const float* __restrict__ c, int n, float* __restrict__ part) {
    __shared__ float sv[256], sq[256];
    const int ch = blockIdx.y, tid = threadIdx.x;
    const float* ap = a + (size_t)ch * n;
    const float* bp = b + (size_t)ch * n;
    const float* cp = c + (size_t)ch * n;
    float s = 0.f, q = 0.f;
    for (int i = blockIdx.x * 256 + tid; i < n; i += NB * 256) {
        float v = ap[i] + bp[i] + cp[i];
        s += v;
        q += v * v;
    }
    sv[tid] = s;
    sq[tid] = q;
    __syncthreads();
    for (int o = 128; o >= 1; o >>= 1) {
        if (tid < o) {
            sv[tid] += sv[tid + o];
            sq[tid] += sq[tid + o];
        }
        __syncthreads();
    }
    if (tid == 0) {
        part[((size_t)ch * NB + blockIdx.x) * 2] = sv[0];
        part[((size_t)ch * NB + blockIdx.x) * 2 + 1] = sq[0];
    }
}

__global__ __launch_bounds__(256) void bn_reduce(
    const float* __restrict__ part, int C, int n, const float* __restrict__ g,
    const float* __restrict__ b, float* __restrict__ params) {
    __shared__ float ss[256], sq[256];
    const int t = threadIdx.x;
    const int P = 256 / C;
    const int c = t % C, r = t / C;
    float s = 0.f, q = 0.f;
    for (int i = r; i < NB; i += P) {
        s += part[((size_t)c * NB + i) * 2];
        q += part[((size_t)c * NB + i) * 2 + 1];
    }
    ss[t] = s;
    sq[t] = q;
    __syncthreads();
    for (int o = P / 2; o >= 1; o >>= 1) {
        if (r < o) {
            ss[t] += ss[t + o * C];
            sq[t] += sq[t + o * C];
        }
        __syncthreads();
    }
    if (r == 0) {
        float inv_n = 1.f / (float)n;
        float mu = ss[t] * inv_n;
        float var = sq[t] * inv_n - mu * mu;
        float sc = g[c] * rsqrtf(var + 1e-5f);
        params[c] = sc;
        params[C + c] = b[c] - mu * sc;
    }
}

// xt[ch][i] = relu((a+b+c)*sc+sh)
__global__ __launch_bounds__(256) void apply3(
    const float* __restrict__ a, const float* __restrict__ b,
    const float* __restrict__ c, const float* __restrict__ par,
    float* __restrict__ out, int n, int C) {
    const int ch = blockIdx.y;
    const float sc = par[ch], sh = par[C + ch];
    const size_t o = (size_t)ch * n;
    for (int i = blockIdx.x * 256 + threadIdx.x; i < n; i += gridDim.x * 256)
        out[o + i] = fmaxf((a[o + i] + b[o + i] + c[o + i]) * sc + sh, 0.f);
}

// out[ch][i] = relu((a+b+c)*sc+sh + res)
__global__ __launch_bounds__(256) void res3(
    const float* __restrict__ a, const float* __restrict__ b,
    const float* __restrict__ c, const float* __restrict__ par,
    const float* __restrict__ res, float* __restrict__ out, int n, int C) {
    const int ch = blockIdx.y;
    const float sc = par[ch], sh = par[C + ch];
    const size_t o = (size_t)ch * n;
    for (int i = blockIdx.x * 256 + threadIdx.x; i < n; i += gridDim.x * 256)
        out[o + i] =
            fmaxf((a[o + i] + b[o + i] + c[o + i]) * sc + sh + res[o + i], 0.f);
}

// out = relu(a+b+c) (flat)
__global__ __launch_bounds__(256) void comb_relu3(
    const float* __restrict__ a, const float* __restrict__ b,
    const float* __restrict__ c, float* __restrict__ out, int total) {
    for (int i = blockIdx.x * 256 + threadIdx.x; i < total; i += gridDim.x * 256)
        out[i] = fmaxf(a[i] + b[i] + c[i], 0.f);
}

// out = a+b+c (flat)
__global__ __launch_bounds__(256) void comb_add3(
    const float* __restrict__ a, const float* __restrict__ b,
    const float* __restrict__ c, float* __restrict__ out, int total) {
    for (int i = blockIdx.x * 256 + threadIdx.x; i < total; i += gridDim.x * 256)
        out[i] = a[i] + b[i] + c[i];
}

// Final: relu((za+zb+zc)*sc+sh + res) SoA -> AoS d_out (smem transpose).
__global__ __launch_bounds__(256) void final3(
    const float* __restrict__ za, const float* __restrict__ zb,
    const float* __restrict__ zc, const float* __restrict__ par,
    const float* __restrict__ res, float* __restrict__ out, int n) {
    __shared__ float t[64 * 65];
    const int R0 = blockIdx.x * 64;
    const int tid = threadIdx.x;
    for (int i = tid; i < 4096; i += 256) {
        int c = i >> 6, r = i & 63;
        int row = R0 + r;
        float v = 0.f;
        if (row < n) {
            size_t o = (size_t)c * n + row;
            v = fmaxf((za[o] + zb[o] + zc[o]) * par[c] + par[64 + c] + res[o],
                      0.f);
        }
        t[c * 65 + r] = v;
    }
    __syncthreads();
    for (int i = tid; i < 4096; i += 256) {
        int r = i >> 6, c = i & 63;
        int row = R0 + r;
        if (row < n) out[(size_t)row * 64 + c] = t[c * 65 + r];
    }
}

// ---------------------------------------------------------------------------
extern "C" void kernel_launch(void* const* d_in, const int* in_sizes, int n_in,
                              void* d_out, int out_size) {
    const float* x_geo = (const float*)d_in[0];
    const float* x_col = (const float*)d_in[1];
    const float* w0 = (const float*)d_in[2];
    const float* w_e1 = (const float*)d_in[3];
    const float* g_e1 = (const float*)d_in[4];
    const float* b_e1 = (const float*)d_in[5];
    const float* w2 = (const float*)d_in[6];
    const float* w_e2 = (const float*)d_in[7];
    const float* g_e2 = (const float*)d_in[8];
    const float* b_e2 = (const float*)d_in[9];
    const int* m1_in = (const int*)d_in[10];
    const int* m2_in = (const int*)d_in[12];
    const int* m3_in = (const int*)d_in[14];
    const int* m4_in = (const int*)d_in[16];

    const int N = in_sizes[0];
    const int n2 = in_sizes[10] / 125;
    const int n4 = in_sizes[14] / 27;

    float *xc, *za, *zb, *zc, *xt, *yb, *part, *par;
    cudaGetSymbolAddress((void**)&xc, g_xc);
    cudaGetSymbolAddress((void**)&za, g_za);
    cudaGetSymbolAddress((void**)&zb, g_zb);
    cudaGetSymbolAddress((void**)&zc, g_zc);
    cudaGetSymbolAddress((void**)&xt, g_xt);
    cudaGetSymbolAddress((void**)&yb, g_y);
    cudaGetSymbolAddress((void**)&part, g_part);
    cudaGetSymbolAddress((void**)&par, g_par);

    const int SM1 = 42 * 4 * 32 * 4;          // 21504
    const int SME1 = 9 * 32 * 32 * 4;         // 36864 (CIN32 SLICE32)
    const int SMC2 = 9 * 32 * 16 * 4;         // 18432 (CIN32 SLICE16)
    const int SME2 = 9 * 64 * 16 * 4;         // 36864 (CIN64 SLICE16)
    cudaFuncSetAttribute(conv1_k, cudaFuncAttributeMaxDynamicSharedMemorySize, SM1);
    cudaFuncSetAttribute(conv_k<32, 32>, cudaFuncAttributeMaxDynamicSharedMemorySize, SME1);
    cudaFuncSetAttribute(conv_k<32, 16>, cudaFuncAttributeMaxDynamicSharedMemorySize, SMC2);
    cudaFuncSetAttribute(conv_k<64, 16>, cudaFuncAttributeMaxDynamicSharedMemorySize, SME2);

    const int gx2 = (n2 + 255) / 256;
    const int gx4 = (n4 + 255) / 256;
    const dim3 gc1(gx2, 1, 3);
    const dim3 ge1(gx2, 1, 3);
    const dim3 gc2(gx4, 4, 3);
    const dim3 ge2(gx4, 4, 3);
    const dim3 gs1(NB, 32), gs2(NB, 64);
    const dim3 ga1((n2 + 2047) / 2048, 32);
    const dim3 ga2((n4 + 2047) / 2048, 64);
    const int t2 = n2 * 32, t4 = n4 * 64;

    // conv1 (k5 s2, 4->32), ksplit 42/42/41 -> relu combine -> xc
    conv1_k<<<gc1, 256, SM1>>>(x_geo, x_col, w0, m1_in, N, n2, 42, 84, za, zb, zc);
    comb_relu3<<<(t2 + 255) / 256 < 2048 ? (t2 + 255) / 256 : 2048, 256>>>(
        za, zb, zc, xc, t2);

    // enc1: 2 BasicBlocks, 32ch; taps 9/9/9
    for (int i = 0; i < 2; i++) {
        const float* wA = w_e1 + (size_t)(i * 2 + 0) * 27 * 32 * 32;
        const float* wB = w_e1 + (size_t)(i * 2 + 1) * 27 * 32 * 32;
        conv_k<32, 32><<<ge1, 256, SME1>>>(xc, wA, m2_in, n2, n2, 32, 27, 9, 18, za, zb, zc);
        stats3<<<gs1, 256>>>(za, zb, zc, n2, part);
        bn_reduce<<<1, 256>>>(part, 32, n2,
                              g_e1 + (size_t)(i * 2) * 32, b_e1 + (size_t)(i * 2) * 32, par);
        apply3<<<ga1, 256>>>(za, zb, zc, par, xt, n2, 32);
        conv_k<32, 32><<<ge1, 256, SME1>>>(xt, wB, m2_in, n2, n2, 32, 27, 9, 18, za, zb, zc);
        stats3<<<gs1, 256>>>(za, zb, zc, n2, part);
        bn_reduce<<<1, 256>>>(part, 32, n2,
                              g_e1 + (size_t)(i * 2 + 1) * 32, b_e1 + (size_t)(i * 2 + 1) * 32, par);
        res3<<<ga1, 256>>>(za, zb, zc, par, xc, xc, n2, 32);
    }

    // conv2 (32 -> 64 onto stride-4 coords), ksplit -> add -> yb
    conv_k<32, 16><<<gc2, 256, SMC2>>>(xc, w2, m3_in, n2, n4, 64, 27, 9, 18, za, zb, zc);
    comb_add3<<<(t4 + 255) / 256 < 2048 ? (t4 + 255) / 256 : 2048, 256>>>(
        za, zb, zc, yb, t4);

    // enc2: 2 BasicBlocks, 64ch
    for (int i = 0; i < 2; i++) {
        const float* wA = w_e2 + (size_t)(i * 2 + 0) * 27 * 64 * 64;
        const float* wB = w_e2 + (size_t)(i * 2 + 1) * 27 * 64 * 64;
        conv_k<64, 16><<<ge2, 256, SME2>>>(yb, wA, m4_in, n4, n4, 64, 27, 9, 18, za, zb, zc);
        stats3<<<gs2, 256>>>(za, zb, zc, n4, part);
        bn_reduce<<<1, 256>>>(part, 64, n4,
                              g_e2 + (size_t)(i * 2) * 64, b_e2 + (size_t)(i * 2) * 64, par);
        apply3<<<ga2, 256>>>(za, zb, zc, par, xt, n4, 64);
        conv_k<64, 16><<<ge2, 256, SME2>>>(xt, wB, m4_in, n4, n4, 64, 27, 9, 18, za, zb, zc);
        stats3<<<gs2, 256>>>(za, zb, zc, n4, part);
        bn_reduce<<<1, 256>>>(part, 64, n4,
                              g_e2 + (size_t)(i * 2 + 1) * 64, b_e2 + (size_t)(i * 2 + 1) * 64, par);
        if (i == 1) {
            final3<<<(n4 + 63) / 64, 256>>>(za, zb, zc, par, yb, (float*)d_out, n4);
        } else {
            res3<<<ga2, 256>>>(za, zb, zc, par, yb, yb, n4, 64);
        }
    }
}

// round 11
// speedup vs baseline: 1.1469x; 1.1469x over previous
#include <cuda_runtime.h>
#include <cstdint>

// ---------------------------------------------------------------------------
// Sparse CNN backbone, fp32. Features in channel-PAIR SoA layout [C/2][n][2]
// (float2 rows). 2-way K-split convs write partials za/zb; BN-reduce folded
// into the elementwise consumers.
// ---------------------------------------------------------------------------

#define MAXN2 80000
#define MAXN4 13824
#define NB 64   // stats blocks per channel

__device__ float g_xc[MAXN2 * 32];
__device__ float g_za[MAXN2 * 32];
__device__ float g_zb[MAXN2 * 32];
__device__ float g_xt[MAXN2 * 32];
__device__ float g_y[MAXN4 * 64];
__device__ float g_part[64 * NB * 2];

typedef unsigned long long ull;

__device__ __forceinline__ ull pack2(float x) {
    ull r;
    asm("mov.b64 %0, {%1, %1};" : "=l"(r) : "f"(x));
    return r;
}
__device__ __forceinline__ void fma2(ull& d, ull a, ull b) {
    asm("fma.rn.f32x2 %0, %1, %2, %0;" : "+l"(d) : "l"(a), "l"(b));
}

// ---------------------------------------------------------------------------
// 2-way K-split conv, pair layout. fT2 [CIN/2][n_in] float2 -> oT2 partials.
// blockIdx.z in {0,1}: taps [0,KH) / [KH,K). blockIdx.y slices COUT.
// Thread = 1 row x SLICE out-channels; 256 rows/CTA.
// ---------------------------------------------------------------------------
template <int CIN, int SLICE>
__global__ __launch_bounds__(256, 3) void conv_k(
    const float2* __restrict__ fT2, const float* __restrict__ W,
    const int* __restrict__ in_map, int n_in, int n_out, int COUT, int K,
    int KH, float2* __restrict__ oTa, float2* __restrict__ oTb) {
    extern __shared__ float sW[];  // [taps][CIN][SLICE]
    const int tid = threadIdx.x;
    const int yoff = blockIdx.y * SLICE;
    const int k0 = blockIdx.z ? KH : 0;
    const int k1 = blockIdx.z ? K : KH;
    const int taps = k1 - k0;
    constexpr int WV = SLICE / 4;

    for (int i = tid; i < taps * CIN * WV; i += 256) {
        int r = i / WV, c4 = (i % WV) * 4;
        reinterpret_cast<float4*>(sW)[i] = *reinterpret_cast<const float4*>(
            W + ((size_t)k0 * CIN + r) * COUT + yoff + c4);
    }
    __syncthreads();

    const int row = blockIdx.x * 256 + tid;
    const bool rowok = row < n_out;
    float2* __restrict__ oT2 = blockIdx.z ? oTb : oTa;

    ull acc[SLICE / 2];
#pragma unroll
    for (int i = 0; i < SLICE / 2; i++) acc[i] = 0ull;

    int idxn = rowok ? __ldg(&in_map[(size_t)k0 * n_out + row]) : n_in;
    for (int k = k0; k < k1; k++) {
        const int idx = idxn;
        if (k + 1 < k1)
            idxn = rowok ? __ldg(&in_map[(size_t)(k + 1) * n_out + row]) : n_in;
        if (idx >= n_in) continue;

        const float* wk = sW + (size_t)(k - k0) * CIN * SLICE;
#pragma unroll
        for (int q = 0; q < CIN / 8; q++) {  // 4 pairs = 8 channels per batch
            float2 x[4];
#pragma unroll
            for (int j = 0; j < 4; j++)
                x[j] = __ldg(fT2 + (size_t)(q * 4 + j) * n_in + idx);
#pragma unroll
            for (int j = 0; j < 4; j++) {
                const int c0 = (q * 4 + j) * 2;
                ull a0 = pack2(x[j].x), a1 = pack2(x[j].y);
                const ulonglong2* w0 =
                    reinterpret_cast<const ulonglong2*>(wk + c0 * SLICE);
                const ulonglong2* w1 =
                    reinterpret_cast<const ulonglong2*>(wk + (c0 + 1) * SLICE);
#pragma unroll
                for (int p = 0; p < SLICE / 4; p++) {
                    ulonglong2 wa = w0[p], wb = w1[p];
                    fma2(acc[2 * p], a0, wa.x);
                    fma2(acc[2 * p + 1], a0, wa.y);
                    fma2(acc[2 * p], a1, wb.x);
                    fma2(acc[2 * p + 1], a1, wb.y);
                }
            }
        }
    }

    if (rowok) {
#pragma unroll
        for (int p = 0; p < SLICE / 2; p++) {
            float2 v = *reinterpret_cast<float2*>(&acc[p]);
            oT2[(size_t)(yoff / 2 + p) * n_out + row] = v;
        }
    }
}

// ---------------------------------------------------------------------------
// First conv, 2-way K-split: CIN=4 (geo ++ col), COUT=32, K=125.
// ---------------------------------------------------------------------------
__global__ __launch_bounds__(256, 3) void conv1_k(
    const float* __restrict__ geo, const float* __restrict__ col,
    const float* __restrict__ W, const int* __restrict__ in_map, int n_in,
    int n_out, int KH, float2* __restrict__ oTa, float2* __restrict__ oTb) {
    extern __shared__ float sm[];
    const int tid = threadIdx.x;
    const int k0 = blockIdx.z ? KH : 0;
    const int k1 = blockIdx.z ? 125 : KH;
    const int taps = k1 - k0;

    for (int i = tid; i < taps * 32; i += 256)
        reinterpret_cast<float4*>(sm)[i] =
            reinterpret_cast<const float4*>(W + (size_t)k0 * 128)[i];
    __syncthreads();

    const int row = blockIdx.x * 256 + tid;
    if (row >= n_out) return;
    float2* __restrict__ oT2 = blockIdx.z ? oTb : oTa;

    ull acc[16];
#pragma unroll
    for (int i = 0; i < 16; i++) acc[i] = 0ull;

    int idxn = __ldg(&in_map[(size_t)k0 * n_out + row]);
    for (int k = k0; k < k1; k++) {
        int idx = idxn;
        if (k + 1 < k1) idxn = __ldg(&in_map[(size_t)(k + 1) * n_out + row]);
        if (idx >= n_in) continue;

        float fr[4];
        fr[0] = __ldg(&geo[idx]);
        fr[1] = __ldg(&col[(size_t)idx * 3]);
        fr[2] = __ldg(&col[(size_t)idx * 3 + 1]);
        fr[3] = __ldg(&col[(size_t)idx * 3 + 2]);
        const float* wk = sm + (k - k0) * 128;
#pragma unroll
        for (int c = 0; c < 4; c++) {
            ull a2 = pack2(fr[c]);
            const ulonglong2* wrow = reinterpret_cast<const ulonglong2*>(wk + c * 32);
#pragma unroll
            for (int p = 0; p < 8; p++) {
                ulonglong2 w = wrow[p];
                fma2(acc[2 * p], a2, w.x);
                fma2(acc[2 * p + 1], a2, w.y);
            }
        }
    }
#pragma unroll
    for (int p = 0; p < 16; p++)
        oT2[(size_t)p * n_out + row] = *reinterpret_cast<float2*>(&acc[p]);
}

// ---------------------------------------------------------------------------
// Stats over (a+b), pair layout. blockIdx.y = channel pair. Writes partials
// for channels 2cp, 2cp+1: part[(c*NB + bx)*2 + {0,1}].
// ---------------------------------------------------------------------------
__global__ __launch_bounds__(256) void stats2(
    const float2* __restrict__ a, const float2* __restrict__ b, int n,
    float* __restrict__ part) {
    __shared__ float s0m[256], q0m[256], s1m[256], q1m[256];
    const int cp = blockIdx.y, tid = threadIdx.x;
    const size_t base = (size_t)cp * n;
    float s0 = 0.f, q0 = 0.f, s1 = 0.f, q1 = 0.f;
    for (int i = blockIdx.x * 256 + tid; i < n; i += NB * 256) {
        float2 va = a[base + i], vb = b[base + i];
        float x = va.x + vb.x, y = va.y + vb.y;
        s0 += x; q0 += x * x;
        s1 += y; q1 += y * y;
    }
    s0m[tid] = s0; q0m[tid] = q0; s1m[tid] = s1; q1m[tid] = q1;
    __syncthreads();
    for (int o = 128; o >= 1; o >>= 1) {
        if (tid < o) {
            s0m[tid] += s0m[tid + o]; q0m[tid] += q0m[tid + o];
            s1m[tid] += s1m[tid + o]; q1m[tid] += q1m[tid + o];
        }
        __syncthreads();
    }
    if (tid == 0) {
        part[((size_t)(2 * cp) * NB + blockIdx.x) * 2] = s0m[0];
        part[((size_t)(2 * cp) * NB + blockIdx.x) * 2 + 1] = q0m[0];
        part[((size_t)(2 * cp + 1) * NB + blockIdx.x) * 2] = s1m[0];
        part[((size_t)(2 * cp + 1) * NB + blockIdx.x) * 2 + 1] = q1m[0];
    }
}

// Warp-folded BN params for channel c (lane-parallel over NB=64 partials).
__device__ __forceinline__ void bn_fold(const float* part, int c, int n,
                                        const float* g, const float* b,
                                        int lane, float* sc_out, float* sh_out) {
    float s = part[((size_t)c * NB + lane) * 2] +
              part[((size_t)c * NB + lane + 32) * 2];
    float q = part[((size_t)c * NB + lane) * 2 + 1] +
              part[((size_t)c * NB + lane + 32) * 2 + 1];
#pragma unroll
    for (int o = 16; o >= 1; o >>= 1) {
        s += __shfl_down_sync(0xffffffffu, s, o);
        q += __shfl_down_sync(0xffffffffu, q, o);
    }
    if (lane == 0) {
        float inv_n = 1.f / (float)n;
        float mu = s * inv_n;
        float var = q * inv_n - mu * mu;
        float sc = __ldg(&g[c]) * rsqrtf(var + 1e-5f);
        *sc_out = sc;
        *sh_out = __ldg(&b[c]) - mu * sc;
    }
}

// xt = relu((a+b)*sc+sh), pair layout; BN reduce folded in prologue.
__global__ __launch_bounds__(256) void apply2(
    const float2* __restrict__ a, const float2* __restrict__ b,
    const float* __restrict__ part, const float* __restrict__ g,
    const float* __restrict__ bb, float2* __restrict__ out, int n) {
    __shared__ float sp[4];  // sc0, sh0, sc1, sh1
    const int cp = blockIdx.y, tid = threadIdx.x;
    const int w = tid >> 5, lane = tid & 31;
    if (w < 2) bn_fold(part, 2 * cp + w, n, g, bb, lane, &sp[2 * w], &sp[2 * w + 1]);
    __syncthreads();
    const float sc0 = sp[0], sh0 = sp[1], sc1 = sp[2], sh1 = sp[3];
    const size_t base = (size_t)cp * n;
    for (int i = blockIdx.x * 256 + tid; i < n; i += gridDim.x * 256) {
        float2 va = a[base + i], vb = b[base + i];
        float2 o;
        o.x = fmaxf((va.x + vb.x) * sc0 + sh0, 0.f);
        o.y = fmaxf((va.y + vb.y) * sc1 + sh1, 0.f);
        out[base + i] = o;
    }
}

// out = relu((a+b)*sc+sh + res), pair layout; BN reduce folded.
__global__ __launch_bounds__(256) void res2(
    const float2* __restrict__ a, const float2* __restrict__ b,
    const float* __restrict__ part, const float* __restrict__ g,
    const float* __restrict__ bb, const float2* __restrict__ res,
    float2* __restrict__ out, int n) {
    __shared__ float sp[4];
    const int cp = blockIdx.y, tid = threadIdx.x;
    const int w = tid >> 5, lane = tid & 31;
    if (w < 2) bn_fold(part, 2 * cp + w, n, g, bb, lane, &sp[2 * w], &sp[2 * w + 1]);
    __syncthreads();
    const float sc0 = sp[0], sh0 = sp[1], sc1 = sp[2], sh1 = sp[3];
    const size_t base = (size_t)cp * n;
    for (int i = blockIdx.x * 256 + tid; i < n; i += gridDim.x * 256) {
        float2 va = a[base + i], vb = b[base + i], vr = res[base + i];
        float2 o;
        o.x = fmaxf((va.x + vb.x) * sc0 + sh0 + vr.x, 0.f);
        o.y = fmaxf((va.y + vb.y) * sc1 + sh1 + vr.y, 0.f);
        out[base + i] = o;
    }
}

// out = relu(a+b) (flat float4)
__global__ __launch_bounds__(256) void comb_relu(
    const float4* __restrict__ a, const float4* __restrict__ b,
    float4* __restrict__ out, int total4) {
    for (int i = blockIdx.x * 256 + threadIdx.x; i < total4; i += gridDim.x * 256) {
        float4 va = a[i], vb = b[i];
        va.x = fmaxf(va.x + vb.x, 0.f);
        va.y = fmaxf(va.y + vb.y, 0.f);
        va.z = fmaxf(va.z + vb.z, 0.f);
        va.w = fmaxf(va.w + vb.w, 0.f);
        out[i] = va;
    }
}

// out = a+b (flat float4)
__global__ __launch_bounds__(256) void comb_add(
    const float4* __restrict__ a, const float4* __restrict__ b,
    float4* __restrict__ out, int total4) {
    for (int i = blockIdx.x * 256 + threadIdx.x; i < total4; i += gridDim.x * 256) {
        float4 va = a[i], vb = b[i];
        va.x += vb.x; va.y += vb.y; va.z += vb.z; va.w += vb.w;
        out[i] = va;
    }
}

// Final: relu((za+zb)*sc+sh + res) pair-SoA -> AoS d_out; BN reduce folded.
__global__ __launch_bounds__(256) void final2(
    const float* __restrict__ za, const float* __restrict__ zb,
    const float* __restrict__ part, const float* __restrict__ g,
    const float* __restrict__ bb, const float* __restrict__ res,
    float* __restrict__ out, int n) {
    __shared__ float t[64 * 65];
    __shared__ float spar[64], sshf[64], rs[256], rq[256];
    const int tid = threadIdx.x;
    // Reduce all 64 channels: 4 threads per channel over 64 partials.
    {
        const int c = tid >> 2, r = tid & 3;
        float S = 0.f, Q = 0.f;
#pragma unroll
        for (int i = 0; i < 16; i++) {
            S += part[((size_t)c * NB + r + 4 * i) * 2];
            Q += part[((size_t)c * NB + r + 4 * i) * 2 + 1];
        }
        rs[tid] = S;
        rq[tid] = Q;
    }
    __syncthreads();
    if (tid < 64) {
        float S = rs[4 * tid] + rs[4 * tid + 1] + rs[4 * tid + 2] + rs[4 * tid + 3];
        float Q = rq[4 * tid] + rq[4 * tid + 1] + rq[4 * tid + 2] + rq[4 * tid + 3];
        float inv_n = 1.f / (float)n;
        float mu = S * inv_n;
        float var = Q * inv_n - mu * mu;
        float sc = __ldg(&g[tid]) * rsqrtf(var + 1e-5f);
        spar[tid] = sc;
        sshf[tid] = __ldg(&bb[tid]) - mu * sc;
    }
    __syncthreads();

    const int R0 = blockIdx.x * 64;
    for (int i = tid; i < 4096; i += 256) {
        int c = i >> 6, r = i & 63;
        int row = R0 + r;
        float v = 0.f;
        if (row < n) {
            size_t o = ((size_t)(c >> 1) * n + row) * 2 + (c & 1);
            v = fmaxf((za[o] + zb[o]) * spar[c] + sshf[c] + res[o], 0.f);
        }
        t[c * 65 + r] = v;
    }
    __syncthreads();
    for (int i = tid; i < 4096; i += 256) {
        int r = i >> 6, c = i & 63;
        int row = R0 + r;
        if (row < n) out[(size_t)row * 64 + c] = t[c * 65 + r];
    }
}

// ---------------------------------------------------------------------------
extern "C" void kernel_launch(void* const* d_in, const int* in_sizes, int n_in,
                              void* d_out, int out_size) {
    const float* x_geo = (const float*)d_in[0];
    const float* x_col = (const float*)d_in[1];
    const float* w0 = (const float*)d_in[2];
    const float* w_e1 = (const float*)d_in[3];
    const float* g_e1 = (const float*)d_in[4];
    const float* b_e1 = (const float*)d_in[5];
    const float* w2 = (const float*)d_in[6];
    const float* w_e2 = (const float*)d_in[7];
    const float* g_e2 = (const float*)d_in[8];
    const float* b_e2 = (const float*)d_in[9];
    const int* m1_in = (const int*)d_in[10];
    const int* m2_in = (const int*)d_in[12];
    const int* m3_in = (const int*)d_in[14];
    const int* m4_in = (const int*)d_in[16];

    const int N = in_sizes[0];
    const int n2 = in_sizes[10] / 125;
    const int n4 = in_sizes[14] / 27;

    float *xc, *za, *zb, *xt, *yb, *part;
    cudaGetSymbolAddress((void**)&xc, g_xc);
    cudaGetSymbolAddress((void**)&za, g_za);
    cudaGetSymbolAddress((void**)&zb, g_zb);
    cudaGetSymbolAddress((void**)&xt, g_xt);
    cudaGetSymbolAddress((void**)&yb, g_y);
    cudaGetSymbolAddress((void**)&part, g_part);

    const int SM1 = 63 * 4 * 32 * 4;          // 32256
    const int SME1 = 14 * 32 * 32 * 4;        // 57344 (CIN32 SLICE32)
    const int SMC2 = 14 * 32 * 16 * 4;        // 28672 (CIN32 SLICE16)
    const int SME2 = 14 * 64 * 16 * 4;        // 57344 (CIN64 SLICE16)
    cudaFuncSetAttribute(conv1_k, cudaFuncAttributeMaxDynamicSharedMemorySize, SM1);
    cudaFuncSetAttribute(conv_k<32, 32>, cudaFuncAttributeMaxDynamicSharedMemorySize, SME1);
    cudaFuncSetAttribute(conv_k<32, 16>, cudaFuncAttributeMaxDynamicSharedMemorySize, SMC2);
    cudaFuncSetAttribute(conv_k<64, 16>, cudaFuncAttributeMaxDynamicSharedMemorySize, SME2);

    const int gx2 = (n2 + 255) / 256;
    const int gx4 = (n4 + 255) / 256;
    const dim3 gc1(gx2, 1, 2);
    const dim3 ge1(gx2, 1, 2);
    const dim3 gc2(gx4, 4, 2);
    const dim3 ge2(gx4, 4, 2);
    const dim3 gs1(NB, 16), gs2(NB, 32);                 // channel pairs
    const dim3 ga1((n2 + 2047) / 2048, 16);
    const dim3 ga2((n4 + 2047) / 2048, 32);
    const int t2 = n2 * 32 / 4, t4 = n4 * 64 / 4;

    // conv1 (k5 s2, 4->32), ksplit 63/62 -> relu combine -> xc
    conv1_k<<<gc1, 256, SM1>>>(x_geo, x_col, w0, m1_in, N, n2, 63,
                               (float2*)za, (float2*)zb);
    comb_relu<<<(t2 + 255) / 256 < 2048 ? (t2 + 255) / 256 : 2048, 256>>>(
        (const float4*)za, (const float4*)zb, (float4*)xc, t2);

    // enc1: 2 BasicBlocks, 32ch; taps 14/13
    for (int i = 0; i < 2; i++) {
        const float* wA = w_e1 + (size_t)(i * 2 + 0) * 27 * 32 * 32;
        const float* wB = w_e1 + (size_t)(i * 2 + 1) * 27 * 32 * 32;
        conv_k<32, 32><<<ge1, 256, SME1>>>((const float2*)xc, wA, m2_in, n2, n2,
                                           32, 27, 14, (float2*)za, (float2*)zb);
        stats2<<<gs1, 256>>>((const float2*)za, (const float2*)zb, n2, part);
        apply2<<<ga1, 256>>>((const float2*)za, (const float2*)zb, part,
                             g_e1 + (size_t)(i * 2) * 32,
                             b_e1 + (size_t)(i * 2) * 32, (float2*)xt, n2);
        conv_k<32, 32><<<ge1, 256, SME1>>>((const float2*)xt, wB, m2_in, n2, n2,
                                           32, 27, 14, (float2*)za, (float2*)zb);
        stats2<<<gs1, 256>>>((const float2*)za, (const float2*)zb, n2, part);
        res2<<<ga1, 256>>>((const float2*)za, (const float2*)zb, part,
                           g_e1 + (size_t)(i * 2 + 1) * 32,
                           b_e1 + (size_t)(i * 2 + 1) * 32, (const float2*)xc,
                           (float2*)xc, n2);
    }

    // conv2 (32 -> 64 onto stride-4 coords), ksplit -> add -> yb
    conv_k<32, 16><<<gc2, 256, SMC2>>>((const float2*)xc, w2, m3_in, n2, n4, 64,
                                       27, 14, (float2*)za, (float2*)zb);
    comb_add<<<(t4 + 255) / 256 < 2048 ? (t4 + 255) / 256 : 2048, 256>>>(
        (const float4*)za, (const float4*)zb, (float4*)yb, t4);

    // enc2: 2 BasicBlocks, 64ch
    for (int i = 0; i < 2; i++) {
        const float* wA = w_e2 + (size_t)(i * 2 + 0) * 27 * 64 * 64;
        const float* wB = w_e2 + (size_t)(i * 2 + 1) * 27 * 64 * 64;
        conv_k<64, 16><<<ge2, 256, SME2>>>((const float2*)yb, wA, m4_in, n4, n4,
                                           64, 27, 14, (float2*)za, (float2*)zb);
        stats2<<<gs2, 256>>>((const float2*)za, (const float2*)zb, n4, part);
        apply2<<<ga2, 256>>>((const float2*)za, (const float2*)zb, part,
                             g_e2 + (size_t)(i * 2) * 64,
                             b_e2 + (size_t)(i * 2) * 64, (float2*)xt, n4);
        conv_k<64, 16><<<ge2, 256, SME2>>>((const float2*)xt, wB, m4_in, n4, n4,
                                           64, 27, 14, (float2*)za, (float2*)zb);
        stats2<<<gs2, 256>>>((const float2*)za, (const float2*)zb, n4, part);
        if (i == 1) {
            final2<<<(n4 + 63) / 64, 256>>>(za, zb, part,
                                            g_e2 + (size_t)(i * 2 + 1) * 64,
                                            b_e2 + (size_t)(i * 2 + 1) * 64, yb,
                                            (float*)d_out, n4);
        } else {
            res2<<<ga2, 256>>>((const float2*)za, (const float2*)zb, part,
                               g_e2 + (size_t)(i * 2 + 1) * 64,
                               b_e2 + (size_t)(i * 2 + 1) * 64,
                               (const float2*)yb, (float2*)yb, n4);
        }
    }
}

// round 12
// speedup vs baseline: 1.3649x; 1.1901x over previous
#include <cuda_runtime.h>
#include <cstdint>

// ---------------------------------------------------------------------------
// Sparse CNN backbone, fp32, channel-pair SoA [C/2][n] float2.
// Convs: 2-way K-split, thread = 2 rows (t, t+256) x SLICE out-channels,
// weight LDS amortized over both rows (LDS:FFMA2 = 1:4), 3 CTAs/SM.
// ---------------------------------------------------------------------------

#define MAXN2 80000
#define MAXN4 13824
#define NB 64

__device__ float g_xc[MAXN2 * 32];
__device__ float g_za[MAXN2 * 32];
__device__ float g_zb[MAXN2 * 32];
__device__ float g_xt[MAXN2 * 32];
__device__ float g_y[MAXN4 * 64];
__device__ float g_part[64 * NB * 2];

typedef unsigned long long ull;

__device__ __forceinline__ ull pack2(float x) {
    ull r;
    asm("mov.b64 %0, {%1, %1};" : "=l"(r) : "f"(x));
    return r;
}
__device__ __forceinline__ void fma2(ull& d, ull a, ull b) {
    asm("fma.rn.f32x2 %0, %1, %2, %0;" : "+l"(d) : "l"(a), "l"(b));
}

// ---------------------------------------------------------------------------
// 2-row, K-split conv. fT2 [CIN/2][n_in] float2 -> oT2 partials.
// blockIdx.z: taps [0,KH)/[KH,K). blockIdx.y slices COUT by SLICE.
// Thread rows: r0 = bx*512 + tid, r1 = r0 + 256.
// ---------------------------------------------------------------------------
template <int CIN, int SLICE>
__global__ __launch_bounds__(256, 3) void conv_k(
    const float2* __restrict__ fT2, const float* __restrict__ W,
    const int* __restrict__ in_map, int n_in, int n_out, int COUT, int K,
    int KH, float2* __restrict__ oTa, float2* __restrict__ oTb) {
    extern __shared__ float sW[];  // [taps][CIN][SLICE]
    const int tid = threadIdx.x;
    const int yoff = blockIdx.y * SLICE;
    const int k0 = blockIdx.z ? KH : 0;
    const int k1 = blockIdx.z ? K : KH;
    const int taps = k1 - k0;
    constexpr int WV = SLICE / 4;

    for (int i = tid; i < taps * CIN * WV; i += 256) {
        int r = i / WV, c4 = (i % WV) * 4;
        reinterpret_cast<float4*>(sW)[i] = *reinterpret_cast<const float4*>(
            W + ((size_t)k0 * CIN + r) * COUT + yoff + c4);
    }
    __syncthreads();

    const int r0 = blockIdx.x * 512 + tid;
    const int r1 = r0 + 256;
    const bool ok0 = r0 < n_out, ok1 = r1 < n_out;
    if (!ok0) return;  // r0 >= n_out implies r1 too (for our grids)
    float2* __restrict__ oT2 = blockIdx.z ? oTb : oTa;

    ull acc0[SLICE / 2], acc1[SLICE / 2];
#pragma unroll
    for (int i = 0; i < SLICE / 2; i++) { acc0[i] = 0ull; acc1[i] = 0ull; }

    int i0n = __ldg(&in_map[(size_t)k0 * n_out + r0]);
    int i1n = ok1 ? __ldg(&in_map[(size_t)k0 * n_out + r1]) : n_in;

    for (int k = k0; k < k1; k++) {
        const int i0 = i0n, i1 = i1n;
        if (k + 1 < k1) {
            const int* mp = in_map + (size_t)(k + 1) * n_out;
            i0n = __ldg(&mp[r0]);
            i1n = ok1 ? __ldg(&mp[r1]) : n_in;
        }
        const bool v0 = i0 < n_in, v1 = i1 < n_in;
        if (__ballot_sync(0xffffffffu, v0 | v1) == 0u) continue;

        const float* wk = sW + (size_t)(k - k0) * CIN * SLICE;
        const float2 z2 = make_float2(0.f, 0.f);
#pragma unroll
        for (int q = 0; q < CIN / 8; q++) {  // 4 pairs per batch
            float2 x0[4], x1[4];
#pragma unroll
            for (int j = 0; j < 4; j++) {
                const float2* colp = fT2 + (size_t)(q * 4 + j) * n_in;
                x0[j] = v0 ? __ldg(colp + i0) : z2;
                x1[j] = v1 ? __ldg(colp + i1) : z2;
            }
#pragma unroll
            for (int j = 0; j < 4; j++) {
                const int c0 = (q * 4 + j) * 2;
                ull a00 = pack2(x0[j].x), a01 = pack2(x0[j].y);
                ull a10 = pack2(x1[j].x), a11 = pack2(x1[j].y);
                const ulonglong2* w0 =
                    reinterpret_cast<const ulonglong2*>(wk + c0 * SLICE);
                const ulonglong2* w1 =
                    reinterpret_cast<const ulonglong2*>(wk + (c0 + 1) * SLICE);
#pragma unroll
                for (int p = 0; p < SLICE / 4; p++) {
                    ulonglong2 wa = w0[p], wb = w1[p];
                    fma2(acc0[2 * p], a00, wa.x);
                    fma2(acc0[2 * p + 1], a00, wa.y);
                    fma2(acc1[2 * p], a10, wa.x);
                    fma2(acc1[2 * p + 1], a10, wa.y);
                    fma2(acc0[2 * p], a01, wb.x);
                    fma2(acc0[2 * p + 1], a01, wb.y);
                    fma2(acc1[2 * p], a11, wb.x);
                    fma2(acc1[2 * p + 1], a11, wb.y);
                }
            }
        }
    }

#pragma unroll
    for (int p = 0; p < SLICE / 2; p++) {
        oT2[(size_t)(yoff / 2 + p) * n_out + r0] =
            *reinterpret_cast<float2*>(&acc0[p]);
    }
    if (ok1) {
#pragma unroll
        for (int p = 0; p < SLICE / 2; p++)
            oT2[(size_t)(yoff / 2 + p) * n_out + r1] =
                *reinterpret_cast<float2*>(&acc1[p]);
    }
}

// ---------------------------------------------------------------------------
// First conv, 2-way K-split: CIN=4 (geo ++ col), COUT=32, K=125.
// ---------------------------------------------------------------------------
__global__ __launch_bounds__(256, 3) void conv1_k(
    const float* __restrict__ geo, const float* __restrict__ col,
    const float* __restrict__ W, const int* __restrict__ in_map, int n_in,
    int n_out, int KH, float2* __restrict__ oTa, float2* __restrict__ oTb) {
    extern __shared__ float sm[];
    const int tid = threadIdx.x;
    const int k0 = blockIdx.z ? KH : 0;
    const int k1 = blockIdx.z ? 125 : KH;
    const int taps = k1 - k0;

    for (int i = tid; i < taps * 32; i += 256)
        reinterpret_cast<float4*>(sm)[i] =
            reinterpret_cast<const float4*>(W + (size_t)k0 * 128)[i];
    __syncthreads();

    const int row = blockIdx.x * 256 + tid;
    if (row >= n_out) return;
    float2* __restrict__ oT2 = blockIdx.z ? oTb : oTa;

    ull acc[16];
#pragma unroll
    for (int i = 0; i < 16; i++) acc[i] = 0ull;

    int idxn = __ldg(&in_map[(size_t)k0 * n_out + row]);
    for (int k = k0; k < k1; k++) {
        int idx = idxn;
        if (k + 1 < k1) idxn = __ldg(&in_map[(size_t)(k + 1) * n_out + row]);
        if (idx >= n_in) continue;

        float fr[4];
        fr[0] = __ldg(&geo[idx]);
        fr[1] = __ldg(&col[(size_t)idx * 3]);
        fr[2] = __ldg(&col[(size_t)idx * 3 + 1]);
        fr[3] = __ldg(&col[(size_t)idx * 3 + 2]);
        const float* wk = sm + (k - k0) * 128;
#pragma unroll
        for (int c = 0; c < 4; c++) {
            ull a2 = pack2(fr[c]);
            const ulonglong2* wrow = reinterpret_cast<const ulonglong2*>(wk + c * 32);
#pragma unroll
            for (int p = 0; p < 8; p++) {
                ulonglong2 w = wrow[p];
                fma2(acc[2 * p], a2, w.x);
                fma2(acc[2 * p + 1], a2, w.y);
            }
        }
    }
#pragma unroll
    for (int p = 0; p < 16; p++)
        oT2[(size_t)p * n_out + row] = *reinterpret_cast<float2*>(&acc[p]);
}

// ---------------------------------------------------------------------------
// Stats over (a+b), pair layout.
// ---------------------------------------------------------------------------
__global__ __launch_bounds__(256) void stats2(
    const float2* __restrict__ a, const float2* __restrict__ b, int n,
    float* __restrict__ part) {
    __shared__ float s0m[256], q0m[256], s1m[256], q1m[256];
    const int cp = blockIdx.y, tid = threadIdx.x;
    const size_t base = (size_t)cp * n;
    float s0 = 0.f, q0 = 0.f, s1 = 0.f, q1 = 0.f;
    for (int i = blockIdx.x * 256 + tid; i < n; i += NB * 256) {
        float2 va = a[base + i], vb = b[base + i];
        float x = va.x + vb.x, y = va.y + vb.y;
        s0 += x; q0 += x * x;
        s1 += y; q1 += y * y;
    }
    s0m[tid] = s0; q0m[tid] = q0; s1m[tid] = s1; q1m[tid] = q1;
    __syncthreads();
    for (int o = 128; o >= 1; o >>= 1) {
        if (tid < o) {
            s0m[tid] += s0m[tid + o]; q0m[tid] += q0m[tid + o];
            s1m[tid] += s1m[tid + o]; q1m[tid] += q1m[tid + o];
        }
        __syncthreads();
    }
    if (tid == 0) {
        part[((size_t)(2 * cp) * NB + blockIdx.x) * 2] = s0m[0];
        part[((size_t)(2 * cp) * NB + blockIdx.x) * 2 + 1] = q0m[0];
        part[((size_t)(2 * cp + 1) * NB + blockIdx.x) * 2] = s1m[0];
        part[((size_t)(2 * cp + 1) * NB + blockIdx.x) * 2 + 1] = q1m[0];
    }
}

// Warp-folded BN params for channel c.
__device__ __forceinline__ void bn_fold(const float* part, int c, int n,
                                        const float* g, const float* b,
                                        int lane, float* sc_out, float* sh_out) {
    float s = part[((size_t)c * NB + lane) * 2] +
              part[((size_t)c * NB + lane + 32) * 2];
    float q = part[((size_t)c * NB + lane) * 2 + 1] +
              part[((size_t)c * NB + lane + 32) * 2 + 1];
#pragma unroll
    for (int o = 16; o >= 1; o >>= 1) {
        s += __shfl_down_sync(0xffffffffu, s, o);
        q += __shfl_down_sync(0xffffffffu, q, o);
    }
    if (lane == 0) {
        float inv_n = 1.f / (float)n;
        float mu = s * inv_n;
        float var = q * inv_n - mu * mu;
        float sc = __ldg(&g[c]) * rsqrtf(var + 1e-5f);
        *sc_out = sc;
        *sh_out = __ldg(&b[c]) - mu * sc;
    }
}

// xt = relu((a+b)*sc+sh); BN reduce folded.
__global__ __launch_bounds__(256) void apply2(
    const float2* __restrict__ a, const float2* __restrict__ b,
    const float* __restrict__ part, const float* __restrict__ g,
    const float* __restrict__ bb, float2* __restrict__ out, int n) {
    __shared__ float sp[4];
    const int cp = blockIdx.y, tid = threadIdx.x;
    const int w = tid >> 5, lane = tid & 31;
    if (w < 2) bn_fold(part, 2 * cp + w, n, g, bb, lane, &sp[2 * w], &sp[2 * w + 1]);
    __syncthreads();
    const float sc0 = sp[0], sh0 = sp[1], sc1 = sp[2], sh1 = sp[3];
    const size_t base = (size_t)cp * n;
    for (int i = blockIdx.x * 256 + tid; i < n; i += gridDim.x * 256) {
        float2 va = a[base + i], vb = b[base + i];
        float2 o;
        o.x = fmaxf((va.x + vb.x) * sc0 + sh0, 0.f);
        o.y = fmaxf((va.y + vb.y) * sc1 + sh1, 0.f);
        out[base + i] = o;
    }
}

// out = relu((a+b)*sc+sh + res); BN reduce folded.
__global__ __launch_bounds__(256) void res2(
    const float2* __restrict__ a, const float2* __restrict__ b,
    const float* __restrict__ part, const float* __restrict__ g,
    const float* __restrict__ bb, const float2* __restrict__ res,
    float2* __restrict__ out, int n) {
    __shared__ float sp[4];
    const int cp = blockIdx.y, tid = threadIdx.x;
    const int w = tid >> 5, lane = tid & 31;
    if (w < 2) bn_fold(part, 2 * cp + w, n, g, bb, lane, &sp[2 * w], &sp[2 * w + 1]);
    __syncthreads();
    const float sc0 = sp[0], sh0 = sp[1], sc1 = sp[2], sh1 = sp[3];
    const size_t base = (size_t)cp * n;
    for (int i = blockIdx.x * 256 + tid; i < n; i += gridDim.x * 256) {
        float2 va = a[base + i], vb = b[base + i], vr = res[base + i];
        float2 o;
        o.x = fmaxf((va.x + vb.x) * sc0 + sh0 + vr.x, 0.f);
        o.y = fmaxf((va.y + vb.y) * sc1 + sh1 + vr.y, 0.f);
        out[base + i] = o;
    }
}

// out = relu(a+b) (flat float4)
__global__ __launch_bounds__(256) void comb_relu(
    const float4* __restrict__ a, const float4* __restrict__ b,
    float4* __restrict__ out, int total4) {
    for (int i = blockIdx.x * 256 + threadIdx.x; i < total4; i += gridDim.x * 256) {
        float4 va = a[i], vb = b[i];
        va.x = fmaxf(va.x + vb.x, 0.f);
        va.y = fmaxf(va.y + vb.y, 0.f);
        va.z = fmaxf(va.z + vb.z, 0.f);
        va.w = fmaxf(va.w + vb.w, 0.f);
        out[i] = va;
    }
}

// out = a+b (flat float4)
__global__ __launch_bounds__(256) void comb_add(
    const float4* __restrict__ a, const float4* __restrict__ b,
    float4* __restrict__ out, int total4) {
    for (int i = blockIdx.x * 256 + threadIdx.x; i < total4; i += gridDim.x * 256) {
        float4 va = a[i], vb = b[i];
        va.x += vb.x; va.y += vb.y; va.z += vb.z; va.w += vb.w;
        out[i] = va;
    }
}

// Final: relu((za+zb)*sc+sh + res) pair-SoA -> AoS d_out; BN reduce folded.
__global__ __launch_bounds__(256) void final2(
    const float* __restrict__ za, const float* __restrict__ zb,
    const float* __restrict__ part, const float* __restrict__ g,
    const float* __restrict__ bb, const float* __restrict__ res,
    float* __restrict__ out, int n) {
    __shared__ float t[64 * 65];
    __shared__ float spar[64], sshf[64], rs[256], rq[256];
    const int tid = threadIdx.x;
    {
        const int c = tid >> 2, r = tid & 3;
        float S = 0.f, Q = 0.f;
#pragma unroll
        for (int i = 0; i < 16; i++) {
            S += part[((size_t)c * NB + r + 4 * i) * 2];
            Q += part[((size_t)c * NB + r + 4 * i) * 2 + 1];
        }
        rs[tid] = S;
        rq[tid] = Q;
    }
    __syncthreads();
    if (tid < 64) {
        float S = rs[4 * tid] + rs[4 * tid + 1] + rs[4 * tid + 2] + rs[4 * tid + 3];
        float Q = rq[4 * tid] + rq[4 * tid + 1] + rq[4 * tid + 2] + rq[4 * tid + 3];
        float inv_n = 1.f / (float)n;
        float mu = S * inv_n;
        float var = Q * inv_n - mu * mu;
        float sc = __ldg(&g[tid]) * rsqrtf(var + 1e-5f);
        spar[tid] = sc;
        sshf[tid] = __ldg(&bb[tid]) - mu * sc;
    }
    __syncthreads();

    const int R0 = blockIdx.x * 64;
    for (int i = tid; i < 4096; i += 256) {
        int c = i >> 6, r = i & 63;
        int row = R0 + r;
        float v = 0.f;
        if (row < n) {
            size_t o = ((size_t)(c >> 1) * n + row) * 2 + (c & 1);
            v = fmaxf((za[o] + zb[o]) * spar[c] + sshf[c] + res[o], 0.f);
        }
        t[c * 65 + r] = v;
    }
    __syncthreads();
    for (int i = tid; i < 4096; i += 256) {
        int r = i >> 6, c = i & 63;
        int row = R0 + r;
        if (row < n) out[(size_t)row * 64 + c] = t[c * 65 + r];
    }
}

// ---------------------------------------------------------------------------
extern "C" void kernel_launch(void* const* d_in, const int* in_sizes, int n_in,
                              void* d_out, int out_size) {
    const float* x_geo = (const float*)d_in[0];
    const float* x_col = (const float*)d_in[1];
    const float* w0 = (const float*)d_in[2];
    const float* w_e1 = (const float*)d_in[3];
    const float* g_e1 = (const float*)d_in[4];
    const float* b_e1 = (const float*)d_in[5];
    const float* w2 = (const float*)d_in[6];
    const float* w_e2 = (const float*)d_in[7];
    const float* g_e2 = (const float*)d_in[8];
    const float* b_e2 = (const float*)d_in[9];
    const int* m1_in = (const int*)d_in[10];
    const int* m2_in = (const int*)d_in[12];
    const int* m3_in = (const int*)d_in[14];
    const int* m4_in = (const int*)d_in[16];

    const int N = in_sizes[0];
    const int n2 = in_sizes[10] / 125;
    const int n4 = in_sizes[14] / 27;

    float *xc, *za, *zb, *xt, *yb, *part;
    cudaGetSymbolAddress((void**)&xc, g_xc);
    cudaGetSymbolAddress((void**)&za, g_za);
    cudaGetSymbolAddress((void**)&zb, g_zb);
    cudaGetSymbolAddress((void**)&xt, g_xt);
    cudaGetSymbolAddress((void**)&yb, g_y);
    cudaGetSymbolAddress((void**)&part, g_part);

    const int SM1 = 63 * 4 * 32 * 4;          // 32256
    const int SME1 = 14 * 32 * 16 * 4;        // 28672 (CIN32 SLICE16)
    const int SMC2 = 14 * 32 * 8 * 4;         // 14336 (CIN32 SLICE8)
    const int SME2 = 14 * 64 * 8 * 4;         // 28672 (CIN64 SLICE8)
    cudaFuncSetAttribute(conv1_k, cudaFuncAttributeMaxDynamicSharedMemorySize, SM1);
    cudaFuncSetAttribute(conv_k<32, 16>, cudaFuncAttributeMaxDynamicSharedMemorySize, SME1);
    cudaFuncSetAttribute(conv_k<32, 8>, cudaFuncAttributeMaxDynamicSharedMemorySize, SMC2);
    cudaFuncSetAttribute(conv_k<64, 8>, cudaFuncAttributeMaxDynamicSharedMemorySize, SME2);

    const int gx2 = (n2 + 255) / 256;         // conv1 rows/CTA = 256
    const int hx2 = (n2 + 511) / 512;         // 2-row conv rows/CTA = 512
    const int hx4 = (n4 + 511) / 512;
    const dim3 gc1(gx2, 1, 2);
    const dim3 ge1(hx2, 2, 2);                // COUT32 / SLICE16
    const dim3 gc2(hx4, 8, 2);                // COUT64 / SLICE8
    const dim3 ge2(hx4, 8, 2);
    const dim3 gs1(NB, 16), gs2(NB, 32);
    const dim3 ga1((n2 + 2047) / 2048, 16);
    const dim3 ga2((n4 + 2047) / 2048, 32);
    const int t2 = n2 * 32 / 4, t4 = n4 * 64 / 4;

    // conv1 (k5 s2, 4->32), ksplit 63/62 -> relu combine -> xc
    conv1_k<<<gc1, 256, SM1>>>(x_geo, x_col, w0, m1_in, N, n2, 63,
                               (float2*)za, (float2*)zb);
    comb_relu<<<(t2 + 255) / 256 < 2048 ? (t2 + 255) / 256 : 2048, 256>>>(
        (const float4*)za, (const float4*)zb, (float4*)xc, t2);

    // enc1: 2 BasicBlocks, 32ch; taps 14/13
    for (int i = 0; i < 2; i++) {
        const float* wA = w_e1 + (size_t)(i * 2 + 0) * 27 * 32 * 32;
        const float* wB = w_e1 + (size_t)(i * 2 + 1) * 27 * 32 * 32;
        conv_k<32, 16><<<ge1, 256, SME1>>>((const float2*)xc, wA, m2_in, n2, n2,
                                           32, 27, 14, (float2*)za, (float2*)zb);
        stats2<<<gs1, 256>>>((const float2*)za, (const float2*)zb, n2, part);
        apply2<<<ga1, 256>>>((const float2*)za, (const float2*)zb, part,
                             g_e1 + (size_t)(i * 2) * 32,
                             b_e1 + (size_t)(i * 2) * 32, (float2*)xt, n2);
        conv_k<32, 16><<<ge1, 256, SME1>>>((const float2*)xt, wB, m2_in, n2, n2,
                                           32, 27, 14, (float2*)za, (float2*)zb);
        stats2<<<gs1, 256>>>((const float2*)za, (const float2*)zb, n2, part);
        res2<<<ga1, 256>>>((const float2*)za, (const float2*)zb, part,
                           g_e1 + (size_t)(i * 2 + 1) * 32,
                           b_e1 + (size_t)(i * 2 + 1) * 32, (const float2*)xc,
                           (float2*)xc, n2);
    }

    // conv2 (32 -> 64 onto stride-4 coords), ksplit -> add -> yb
    conv_k<32, 8><<<gc2, 256, SMC2>>>((const float2*)xc, w2, m3_in, n2, n4, 64,
                                      27, 14, (float2*)za, (float2*)zb);
    comb_add<<<(t4 + 255) / 256 < 2048 ? (t4 + 255) / 256 : 2048, 256>>>(
        (const float4*)za, (const float4*)zb, (float4*)yb, t4);

    // enc2: 2 BasicBlocks, 64ch
    for (int i = 0; i < 2; i++) {
        const float* wA = w_e2 + (size_t)(i * 2 + 0) * 27 * 64 * 64;
        const float* wB = w_e2 + (size_t)(i * 2 + 1) * 27 * 64 * 64;
        conv_k<64, 8><<<ge2, 256, SME2>>>((const float2*)yb, wA, m4_in, n4, n4,
                                          64, 27, 14, (float2*)za, (float2*)zb);
        stats2<<<gs2, 256>>>((const float2*)za, (const float2*)zb, n4, part);
        apply2<<<ga2, 256>>>((const float2*)za, (const float2*)zb, part,
                             g_e2 + (size_t)(i * 2) * 64,
                             b_e2 + (size_t)(i * 2) * 64, (float2*)xt, n4);
        conv_k<64, 8><<<ge2, 256, SME2>>>((const float2*)xt, wB, m4_in, n4, n4,
                                          64, 27, 14, (float2*)za, (float2*)zb);
        stats2<<<gs2, 256>>>((const float2*)za, (const float2*)zb, n4, part);
        if (i == 1) {
            final2<<<(n4 + 63) / 64, 256>>>(za, zb, part,
                                            g_e2 + (size_t)(i * 2 + 1) * 64,
                                            b_e2 + (size_t)(i * 2 + 1) * 64, yb,
                                            (float*)d_out, n4);
        } else {
            res2<<<ga2, 256>>>((const float2*)za, (const float2*)zb, part,
                               g_e2 + (size_t)(i * 2 + 1) * 64,
                               b_e2 + (size_t)(i * 2 + 1) * 64,
                               (const float2*)yb, (float2*)yb, n4);
        }
    }
}